// round 3
// baseline (speedup 1.0000x reference)
#include <cuda_runtime.h>

#define N_NODES 100000
#define N_EDGES 1600000
#define F_IN    128
#define F_HID   64
#define F_OUT   47
#define F_OUT_P 48   // padded

// ---------------- scratch (allocation-guard compliant) ----------------
__device__ __align__(16) float g_xw1 [N_NODES * F_HID];
__device__ __align__(16) float g_agg1[N_NODES * F_HID];
__device__ __align__(16) float g_xw2 [N_NODES * F_OUT_P];
__device__ __align__(16) float g_agg2[N_NODES * F_OUT_P];
__device__ float g_deg   [N_NODES];
__device__ float g_dinv  [N_NODES];
__device__ float g_invdeg[N_NODES];
__device__ float g_norm  [N_EDGES];

// Vectorized reduction (sm_90+): 1 RED op moves 16B
__device__ __forceinline__ void red_add_v4(float* addr, float4 v) {
    asm volatile("red.global.add.v4.f32 [%0], {%1,%2,%3,%4};"
                 :: "l"(addr), "f"(v.x), "f"(v.y), "f"(v.z), "f"(v.w)
                 : "memory");
}

// ---------------- degree / norm ----------------
__global__ void k_deg_init() {
    int i = blockIdx.x * 256 + threadIdx.x;
    if (i < N_NODES) g_deg[i] = 1.0f;          // A + I: start at 1
}

__global__ void k_deg_count(const int* __restrict__ dst) {
    int e = blockIdx.x * 256 + threadIdx.x;
    if (e < N_EDGES) atomicAdd(&g_deg[dst[e]], 1.0f);   // compiles to REDG
}

__global__ void k_deg_fin() {
    int i = blockIdx.x * 256 + threadIdx.x;
    if (i < N_NODES) {
        float d = g_deg[i];
        g_dinv[i]   = rsqrtf(d);
        g_invdeg[i] = 1.0f / d;
    }
}

__global__ void k_norm(const int* __restrict__ src, const int* __restrict__ dst) {
    int e = blockIdx.x * 256 + threadIdx.x;
    if (e < N_EDGES) g_norm[e] = g_dinv[src[e]] * g_dinv[dst[e]];
}

// ---------------- GEMM1: xw1[N,64] = x[N,128] @ W1[128,64] ----------------
// 256 thr: col = t&63, rowgroup rg = t>>6, each thread -> 4 rows x 1 col.
__global__ void k_gemm1(const float* __restrict__ x, const float* __restrict__ W1) {
    __shared__ float  ws[F_IN * F_HID];       // 32 KB
    __shared__ float4 xs[16][F_IN / 4];       // 16 rows x 128 f32 = 8 KB
    int t = threadIdx.x;
    for (int i = t; i < F_IN * F_HID; i += 256) ws[i] = W1[i];
    int row0 = blockIdx.x * 16;
    const float4* xg = (const float4*)x + (size_t)row0 * (F_IN / 4);
    for (int i = t; i < 16 * (F_IN / 4); i += 256) xs[i >> 5][i & 31] = xg[i];
    __syncthreads();

    int col = t & 63;
    int rg  = t >> 6;                          // 0..3
    float acc0 = 0.f, acc1 = 0.f, acc2 = 0.f, acc3 = 0.f;
#pragma unroll 8
    for (int k4 = 0; k4 < F_IN / 4; ++k4) {
        float4 a0 = xs[rg * 4 + 0][k4];        // broadcast LDS within warp
        float4 a1 = xs[rg * 4 + 1][k4];
        float4 a2 = xs[rg * 4 + 2][k4];
        float4 a3 = xs[rg * 4 + 3][k4];
        int k = k4 * 4;
        float w0 = ws[(k + 0) * F_HID + col];  // conflict-free LDS
        float w1 = ws[(k + 1) * F_HID + col];
        float w2 = ws[(k + 2) * F_HID + col];
        float w3 = ws[(k + 3) * F_HID + col];
        acc0 += a0.x * w0; acc0 += a0.y * w1; acc0 += a0.z * w2; acc0 += a0.w * w3;
        acc1 += a1.x * w0; acc1 += a1.y * w1; acc1 += a1.z * w2; acc1 += a1.w * w3;
        acc2 += a2.x * w0; acc2 += a2.y * w1; acc2 += a2.z * w2; acc2 += a2.w * w3;
        acc3 += a3.x * w0; acc3 += a3.y * w1; acc3 += a3.z * w2; acc3 += a3.w * w3;
    }
    int r = row0 + rg * 4;
    g_xw1[(size_t)(r + 0) * F_HID + col] = acc0;
    g_xw1[(size_t)(r + 1) * F_HID + col] = acc1;
    g_xw1[(size_t)(r + 2) * F_HID + col] = acc2;
    g_xw1[(size_t)(r + 3) * F_HID + col] = acc3;
}

// ---------------- self-loop init: agg = xw * (1/deg) ----------------
__global__ void k_self1() {
    int i = blockIdx.x * 256 + threadIdx.x;
    if (i >= N_NODES * (F_HID / 4)) return;
    float w = g_invdeg[i >> 4];
    float4 v = ((const float4*)g_xw1)[i];
    v.x *= w; v.y *= w; v.z *= w; v.w *= w;
    ((float4*)g_agg1)[i] = v;
}

__global__ void k_self2() {
    int i = blockIdx.x * 256 + threadIdx.x;
    if (i >= N_NODES * (F_OUT_P / 4)) return;
    float w = g_invdeg[i / (F_OUT_P / 4)];
    float4 v = ((const float4*)g_xw2)[i];
    v.x *= w; v.y *= w; v.z *= w; v.w *= w;
    ((float4*)g_agg2)[i] = v;
}

// ---------------- edge scatter: agg[dst] += xw[src] * norm ----------------
// flat (edge, float4-chunk) mapping: 16 consecutive threads share one edge
// -> the 256B gather of that edge's row is fully coalesced.
__global__ void k_scatter1(const int* __restrict__ src, const int* __restrict__ dst) {
    int idx = blockIdx.x * 256 + threadIdx.x;
    if (idx >= N_EDGES * 16) return;
    int e = idx >> 4, c = idx & 15;
    int s = src[e], d = dst[e];
    float w = g_norm[e];
    float4 v = ((const float4*)g_xw1)[(size_t)s * 16 + c];
    v.x *= w; v.y *= w; v.z *= w; v.w *= w;
    red_add_v4((float*)((float4*)g_agg1 + ((size_t)d * 16 + c)), v);
}

__global__ void k_scatter2(const int* __restrict__ src, const int* __restrict__ dst) {
    int idx = blockIdx.x * 256 + threadIdx.x;
    if (idx >= N_EDGES * 12) return;
    int e = idx / 12, c = idx - e * 12;
    int s = src[e], d = dst[e];
    float w = g_norm[e];
    float4 v = ((const float4*)g_xw2)[(size_t)s * 12 + c];
    v.x *= w; v.y *= w; v.z *= w; v.w *= w;
    red_add_v4((float*)((float4*)g_agg2 + ((size_t)d * 12 + c)), v);
}

// ---------------- GEMM2: xw2[N,48] = relu(agg1 + b1) @ W2pad[64,48] ----------------
// 192 thr: col = t%48, rg = t/48, each thread -> 4 rows x 1 col.
__global__ void k_gemm2(const float* __restrict__ b1, const float* __restrict__ W2) {
    __shared__ float  ws[F_HID * F_OUT_P];    // 12 KB (col 47 zero-padded)
    __shared__ float4 xs[16][F_HID / 4];      // 4 KB
    int t = threadIdx.x;
    for (int i = t; i < F_HID * F_OUT_P; i += 192) {
        int k = i / F_OUT_P, c = i - k * F_OUT_P;
        ws[i] = (c < F_OUT) ? W2[k * F_OUT + c] : 0.0f;
    }
    int row0 = blockIdx.x * 16;
    const float4* hb  = (const float4*)g_agg1 + (size_t)row0 * (F_HID / 4);
    const float4* b1v = (const float4*)b1;
    for (int i = t; i < 16 * (F_HID / 4); i += 192) {
        float4 v = hb[i];
        float4 b = b1v[i & 15];
        float4 h;
        h.x = fmaxf(v.x + b.x, 0.f);
        h.y = fmaxf(v.y + b.y, 0.f);
        h.z = fmaxf(v.z + b.z, 0.f);
        h.w = fmaxf(v.w + b.w, 0.f);
        xs[i >> 4][i & 15] = h;
    }
    __syncthreads();

    int col = t % F_OUT_P;
    int rg  = t / F_OUT_P;                    // 0..3
    float acc0 = 0.f, acc1 = 0.f, acc2 = 0.f, acc3 = 0.f;
#pragma unroll 8
    for (int k4 = 0; k4 < F_HID / 4; ++k4) {
        float4 a0 = xs[rg * 4 + 0][k4];
        float4 a1 = xs[rg * 4 + 1][k4];
        float4 a2 = xs[rg * 4 + 2][k4];
        float4 a3 = xs[rg * 4 + 3][k4];
        int k = k4 * 4;
        float w0 = ws[(k + 0) * F_OUT_P + col];
        float w1 = ws[(k + 1) * F_OUT_P + col];
        float w2 = ws[(k + 2) * F_OUT_P + col];
        float w3 = ws[(k + 3) * F_OUT_P + col];
        acc0 += a0.x * w0; acc0 += a0.y * w1; acc0 += a0.z * w2; acc0 += a0.w * w3;
        acc1 += a1.x * w0; acc1 += a1.y * w1; acc1 += a1.z * w2; acc1 += a1.w * w3;
        acc2 += a2.x * w0; acc2 += a2.y * w1; acc2 += a2.z * w2; acc2 += a2.w * w3;
        acc3 += a3.x * w0; acc3 += a3.y * w1; acc3 += a3.z * w2; acc3 += a3.w * w3;
    }
    int r = row0 + rg * 4;
    g_xw2[(size_t)(r + 0) * F_OUT_P + col] = acc0;
    g_xw2[(size_t)(r + 1) * F_OUT_P + col] = acc1;
    g_xw2[(size_t)(r + 2) * F_OUT_P + col] = acc2;
    g_xw2[(size_t)(r + 3) * F_OUT_P + col] = acc3;
}

// ---------------- log_softmax over 47 cols, one warp per row ----------------
__global__ void k_out(const float* __restrict__ b2, float* __restrict__ out) {
    int warp = threadIdx.x >> 5;
    int lane = threadIdx.x & 31;
    int row  = blockIdx.x * 8 + warp;
    if (row >= N_NODES) return;
    const float* r = g_agg2 + (size_t)row * F_OUT_P;
    int  c1  = lane + 32;
    bool ok1 = (c1 < F_OUT);
    float v0 = r[lane] + b2[lane];
    float v1 = ok1 ? (r[c1] + b2[c1]) : -1e30f;

    float m = fmaxf(v0, v1);
#pragma unroll
    for (int off = 16; off > 0; off >>= 1)
        m = fmaxf(m, __shfl_xor_sync(0xffffffffu, m, off));

    float s = expf(v0 - m) + (ok1 ? expf(v1 - m) : 0.0f);
#pragma unroll
    for (int off = 16; off > 0; off >>= 1)
        s += __shfl_xor_sync(0xffffffffu, s, off);

    float ls = m + logf(s);
    out[(size_t)row * F_OUT + lane] = v0 - ls;
    if (ok1) out[(size_t)row * F_OUT + c1] = v1 - ls;
}

// ---------------- launch ----------------
extern "C" void kernel_launch(void* const* d_in, const int* in_sizes, int n_in,
                              void* d_out, int out_size) {
    const float* x  = (const float*)d_in[0];
    const int*   ei = (const int*)  d_in[1];
    const float* W1 = (const float*)d_in[2];
    const float* b1 = (const float*)d_in[3];
    const float* W2 = (const float*)d_in[4];
    const float* b2 = (const float*)d_in[5];
    float* out = (float*)d_out;
    const int* src = ei;
    const int* dst = ei + N_EDGES;

    k_deg_init <<<(N_NODES + 255) / 256, 256>>>();
    k_deg_count<<<(N_EDGES + 255) / 256, 256>>>(dst);
    k_deg_fin  <<<(N_NODES + 255) / 256, 256>>>();
    k_norm     <<<(N_EDGES + 255) / 256, 256>>>(src, dst);

    k_gemm1    <<<N_NODES / 16, 256>>>(x, W1);
    k_self1    <<<(N_NODES * 16 + 255) / 256, 256>>>();
    k_scatter1 <<<(N_EDGES * 16 + 255) / 256, 256>>>(src, dst);

    k_gemm2    <<<N_NODES / 16, 192>>>(b1, W2);
    k_self2    <<<(N_NODES * 12 + 255) / 256, 256>>>();
    k_scatter2 <<<(N_EDGES * 12 + 255) / 256, 256>>>(src, dst);

    k_out      <<<(N_NODES + 7) / 8, 256>>>(b2, out);
}